// round 9
// baseline (speedup 1.0000x reference)
#include <cuda_runtime.h>
#include <cuda_bf16.h>
#include <math.h>
#include <stdint.h>

#define N_NODES 30000
#define E_RAW   480000
#define E_TOT   (E_RAW + N_NODES)
#define MAXH    4
#define MAXHC   512
#define TPB     256
#define MAXK    512
// packed transposed-weight regions (elements): L0 256x512, L1 512x512, L2 512x256, L3 256x64
#define WOFF0 0
#define WOFF1 131072
#define WOFF2 393216
#define WOFF3 524288
#define WTOT  540672

// ---------------- scratch ----------------------------------------------------
__device__ float g_h[N_NODES * MAXHC];
__device__ float g_asrc[N_NODES * MAXH];
__device__ float g_adst[N_NODES * MAXH];
__device__ int   g_src[E_TOT];
__device__ int   g_dst[E_TOT];
__device__ int   g_csr_src[E_TOT];
__device__ int   g_deg[N_NODES];
__device__ int   g_rowptr[N_NODES + 1];
__device__ int   g_cursor[N_NODES];
__device__ int   g_is64;
__device__ __align__(16) __nv_bfloat16 g_Ahi[N_NODES * MAXK];
__device__ __align__(16) __nv_bfloat16 g_Alo[N_NODES * MAXK];
__device__ __align__(16) __nv_bfloat16 g_Whi[WTOT];
__device__ __align__(16) __nv_bfloat16 g_Wlo[WTOT];
#define SB 128
#define NSB ((N_NODES + SB - 1) / SB)
__device__ int g_bsum[NSB];

// ---------------- helpers -----------------------------------------------------
__device__ __forceinline__ uint32_t smem_u32(const void* p) {
    uint32_t a;
    asm("{ .reg .u64 t; cvta.to.shared.u64 t, %1; cvt.u32.u64 %0, t; }" : "=r"(a) : "l"(p));
    return a;
}
__device__ __forceinline__ uint32_t sw128(uint32_t off) { return off ^ ((off >> 3) & 0x70); }
__device__ __forceinline__ int clampN(int v) {
    return v < 0 ? 0 : (v >= N_NODES ? N_NODES - 1 : v);
}
#define LDSM_X4(r0, r1, r2, r3, addr) \
    asm volatile("ldmatrix.sync.aligned.m8n8.x4.shared.b16 {%0,%1,%2,%3}, [%4];" \
                 : "=r"(r0), "=r"(r1), "=r"(r2), "=r"(r3) : "r"(addr))
#define CP_ASYNC16(saddr, gptr, bytes) \
    asm volatile("cp.async.cg.shared.global [%0], [%1], 16, %2;" \
                 :: "r"(saddr), "l"(gptr), "r"(bytes))
#define CP_COMMIT()  asm volatile("cp.async.commit_group;" ::: "memory")
#define CP_WAIT(n)   asm volatile("cp.async.wait_group %0;" :: "n"(n) : "memory")
__device__ __forceinline__ void mma16816(float* c, const uint32_t* a, const uint32_t* b) {
    asm volatile(
        "mma.sync.aligned.m16n8k16.row.col.f32.bf16.bf16.f32 "
        "{%0,%1,%2,%3}, {%4,%5,%6,%7}, {%8,%9}, {%0,%1,%2,%3};"
        : "+f"(c[0]), "+f"(c[1]), "+f"(c[2]), "+f"(c[3])
        : "r"(a[0]), "r"(a[1]), "r"(a[2]), "r"(a[3]), "r"(b[0]), "r"(b[1]));
}

// ---------------- preprocessing ----------------------------------------------
__global__ void detect_dtype_kernel(const int* __restrict__ ei32) {
    int all_odd_zero = 1;
    for (int i = 0; i < 32; i++)
        if (ei32[2 * i + 1] != 0) { all_odd_zero = 0; break; }
    g_is64 = all_odd_zero;
}
__global__ void zero_deg_kernel() {
    int i = blockIdx.x * blockDim.x + threadIdx.x;
    if (i < N_NODES) g_deg[i] = 0;
}
__global__ void build_edges_kernel(const void* __restrict__ ei_raw) {
    int i = blockIdx.x * blockDim.x + threadIdx.x;
    if (i >= E_TOT) return;
    int s, d;
    if (i < E_RAW) {
        if (g_is64) {
            const long long* e = (const long long*)ei_raw;
            s = (int)e[i]; d = (int)e[E_RAW + i];
        } else {
            const int* e = (const int*)ei_raw;
            s = e[i]; d = e[E_RAW + i];
        }
        s = clampN(s); d = clampN(d);
    } else {
        s = i - E_RAW; d = s;
    }
    g_src[i] = s; g_dst[i] = d;
    atomicAdd(&g_deg[d], 1);
}
__global__ void scan1_kernel() {
    __shared__ int sm[SB];
    int i = blockIdx.x * SB + threadIdx.x;
    sm[threadIdx.x] = (i < N_NODES) ? g_deg[i] : 0;
    __syncthreads();
    for (int off = SB / 2; off > 0; off >>= 1) {
        if (threadIdx.x < off) sm[threadIdx.x] += sm[threadIdx.x + off];
        __syncthreads();
    }
    if (threadIdx.x == 0) g_bsum[blockIdx.x] = sm[0];
}
__global__ void scan2_kernel() {
    __shared__ int sm[256];
    int t = threadIdx.x;
    int v = (t < NSB) ? g_bsum[t] : 0;
    sm[t] = v;
    __syncthreads();
    for (int off = 1; off < 256; off <<= 1) {
        int u = (t >= off) ? sm[t - off] : 0;
        __syncthreads();
        sm[t] += u;
        __syncthreads();
    }
    if (t < NSB) g_bsum[t] = sm[t] - v;
}
__global__ void scan3_kernel() {
    __shared__ int sm[SB];
    int t = threadIdx.x;
    int i = blockIdx.x * SB + t;
    int d = (i < N_NODES) ? g_deg[i] : 0;
    sm[t] = d;
    __syncthreads();
    for (int off = 1; off < SB; off <<= 1) {
        int u = (t >= off) ? sm[t - off] : 0;
        __syncthreads();
        sm[t] += u;
        __syncthreads();
    }
    int excl = g_bsum[blockIdx.x] + sm[t] - d;
    if (i < N_NODES) { g_rowptr[i] = excl; g_cursor[i] = excl; }
    if (blockIdx.x == 0 && t == 0) g_rowptr[N_NODES] = E_TOT;
}
__global__ void scatter_kernel() {
    int e = blockIdx.x * blockDim.x + threadIdx.x;
    if (e >= E_TOT) return;
    int d = g_dst[e];
    int pos = atomicAdd(&g_cursor[d], 1);
    g_csr_src[pos] = g_src[e];
}

// ---------------- fp32 -> bf16 hi/lo split (layer-0 input only) --------------
__global__ void split_kernel(const float* __restrict__ src, int total4) {
    int i = blockIdx.x * blockDim.x + threadIdx.x;
    if (i >= total4) return;
    float4 v = ((const float4*)src)[i];
    __nv_bfloat16 h0 = __float2bfloat16(v.x), h1 = __float2bfloat16(v.y);
    __nv_bfloat16 h2 = __float2bfloat16(v.z), h3 = __float2bfloat16(v.w);
    __nv_bfloat16 l0 = __float2bfloat16(v.x - __bfloat162float(h0));
    __nv_bfloat16 l1 = __float2bfloat16(v.y - __bfloat162float(h1));
    __nv_bfloat16 l2 = __float2bfloat16(v.z - __bfloat162float(h2));
    __nv_bfloat16 l3 = __float2bfloat16(v.w - __bfloat162float(h3));
    ((__nv_bfloat162*)g_Ahi)[2 * i + 0] = __nv_bfloat162(h0, h1);
    ((__nv_bfloat162*)g_Ahi)[2 * i + 1] = __nv_bfloat162(h2, h3);
    ((__nv_bfloat162*)g_Alo)[2 * i + 0] = __nv_bfloat162(l0, l1);
    ((__nv_bfloat162*)g_Alo)[2 * i + 1] = __nv_bfloat162(l2, l3);
}

// ---------------- ONE fused transpose+split for all 4 weight matrices --------
// tiles: L0 (N512,K256)->128, L1 (512,512)->256, L2 (256,512)->128, L3 (64,256)->16
__global__ void wsplit_all_kernel(const float* __restrict__ W0, const float* __restrict__ W1,
                                  const float* __restrict__ W2, const float* __restrict__ W3) {
    __shared__ float t[32][33];
    int b = blockIdx.x;
    const float* W; int K, N; size_t off; int local;
    if (b < 128)      { W = W0; K = 256; N = 512; off = WOFF0; local = b; }
    else if (b < 384) { W = W1; K = 512; N = 512; off = WOFF1; local = b - 128; }
    else if (b < 512) { W = W2; K = 512; N = 256; off = WOFF2; local = b - 384; }
    else              { W = W3; K = 256; N = 64;  off = WOFF3; local = b - 512; }
    int ntiles = N / 32;
    int nb = (local % ntiles) * 32, kb = (local / ntiles) * 32;
    int tx = threadIdx.x, ty = threadIdx.y;   // (32, 8)
#pragma unroll
    for (int j = 0; j < 4; j++)
        t[ty + j * 8][tx] = W[(size_t)(kb + ty + j * 8) * N + nb + tx];
    __syncthreads();
#pragma unroll
    for (int j = 0; j < 4; j++) {
        int n = nb + ty + j * 8, k = kb + tx;
        float v = t[tx][ty + j * 8];
        __nv_bfloat16 h = __float2bfloat16(v);
        g_Whi[off + (size_t)n * K + k] = h;
        g_Wlo[off + (size_t)n * K + k] = __float2bfloat16(v - __bfloat162float(h));
    }
}

// ---------------- HMMA bf16 GEMM (3-pass split, 3-stage cp.async, fused alpha)
template <int BN>
__global__ __launch_bounds__(256, 2) void mma_gemm_kernel(
        float* __restrict__ D, const float* __restrict__ a_s,
        const float* __restrict__ a_d, int M, int N, int K, int H, int C, int boff) {
    extern __shared__ __align__(1024) char smem[];
    char* Abuf[3] = { smem, smem + 16384, smem + 32768 };
    char* Bbuf[3] = { smem + 49152, smem + 49152 + BN * 128, smem + 49152 + 2 * BN * 128 };

    const int tid = threadIdx.x;
    const int wid = tid >> 5, lane = tid & 31;
    const int rowBase = blockIdx.y * 128;
    const int colBase = blockIdx.x * BN;
    const int wr = wid >> 2, wc = wid & 3;      // warp grid 2 x 4
    constexpr int WN = BN / 4;
    constexpr int NT = WN / 8;
    const int warpRow = wr * 64, warpCol = wc * WN;

    float acc[4][NT][4];
#pragma unroll
    for (int i = 0; i < 4; i++)
#pragma unroll
        for (int j = 0; j < NT; j++)
#pragma unroll
            for (int q = 0; q < 4; q++) acc[i][j][q] = 0.f;

    const int kch = K / 64;
    const int NCH = 3 * kch;

    auto load_async = [&](int i, int buf) {
        int pass = i / kch, kc = i - pass * kch;
        const __nv_bfloat16* Asrc = (pass == 2) ? g_Alo : g_Ahi;
        const __nv_bfloat16* Bsrc = ((pass == 1) ? g_Wlo : g_Whi) + boff;
        uint32_t sAu = smem_u32(Abuf[buf]), sBu = smem_u32(Bbuf[buf]);
#pragma unroll
        for (int j = 0; j < 4; j++) {
            int q = tid + j * 256;
            int r = q >> 3, c16 = q & 7;
            const void* src = Asrc + (size_t)(rowBase + r) * K + kc * 64 + c16 * 8;
            int bytes = (rowBase + r < M) ? 16 : 0;
            CP_ASYNC16(sAu + sw128(r * 128 + c16 * 16), src, bytes);
        }
#pragma unroll
        for (int j = 0; j < BN / 32; j++) {
            int q = tid + j * 256;
            int r = q >> 3, c16 = q & 7;
            const void* src = Bsrc + (size_t)(colBase + r) * K + kc * 64 + c16 * 8;
            CP_ASYNC16(sBu + sw128(r * 128 + c16 * 16), src, 16);
        }
        CP_COMMIT();
    };

    load_async(0, 0);
    load_async(1, 1);

    const int g = lane >> 3;
    const int l7 = lane & 7;

    for (int i = 0; i < NCH; i++) {
        int cur = i % 3;
        if (i + 2 < NCH) { load_async(i + 2, (i + 2) % 3); CP_WAIT(2); }
        else if (i + 1 < NCH) CP_WAIT(1);
        else CP_WAIT(0);
        __syncthreads();

        uint32_t aBase = smem_u32(Abuf[cur]);
        uint32_t bBase = smem_u32(Bbuf[cur]);
#pragma unroll
        for (int kk = 0; kk < 4; kk++) {
            uint32_t af[4][4];
#pragma unroll
            for (int mt = 0; mt < 4; mt++) {
                int row = warpRow + mt * 16 + l7 + ((g & 1) ? 8 : 0);
                int kb = (kk * 16 + ((g >= 2) ? 8 : 0)) * 2;
                uint32_t addr = aBase + sw128((uint32_t)(row * 128 + kb));
                LDSM_X4(af[mt][0], af[mt][1], af[mt][2], af[mt][3], addr);
            }
            uint32_t bf[NT][2];
#pragma unroll
            for (int np = 0; np < NT / 2; np++) {
                int row = warpCol + np * 16 + l7 + ((g >= 2) ? 8 : 0);
                int kb = (kk * 16 + ((g & 1) ? 8 : 0)) * 2;
                uint32_t addr = bBase + sw128((uint32_t)(row * 128 + kb));
                uint32_t r0, r1, r2, r3;
                LDSM_X4(r0, r1, r2, r3, addr);
                bf[np * 2][0] = r0;  bf[np * 2][1] = r1;
                bf[np * 2 + 1][0] = r2; bf[np * 2 + 1][1] = r3;
            }
#pragma unroll
            for (int mt = 0; mt < 4; mt++)
#pragma unroll
                for (int nt = 0; nt < NT; nt++)
                    mma16816(acc[mt][nt], af[mt], bf[nt]);
        }
        __syncthreads();
    }

    // ---------------- epilogue: store D + fused alpha dots -------------------
    const int qr = lane >> 2, qc = lane & 3;
#pragma unroll
    for (int mt = 0; mt < 4; mt++) {
        int r0 = rowBase + warpRow + mt * 16 + qr;
#pragma unroll
        for (int nt = 0; nt < NT; nt++) {
            int col = colBase + warpCol + nt * 8 + qc * 2;
            if (r0 < M)
                *(float2*)&D[(size_t)r0 * N + col] = make_float2(acc[mt][nt][0], acc[mt][nt][1]);
            if (r0 + 8 < M)
                *(float2*)&D[(size_t)(r0 + 8) * N + col] = make_float2(acc[mt][nt][2], acc[mt][nt][3]);
        }
    }

    float* sAs   = (float*)smem;
    float* sAd   = sAs + BN;
    float* sRedS = sAd + BN;
    float* sRedD = sRedS + 4 * 128;
    if (tid < BN) {
        sAs[tid] = a_s[colBase + tid];
        sAd[tid] = a_d[colBase + tid];
    }
    __syncthreads();

#pragma unroll
    for (int mt = 0; mt < 4; mt++) {
        float s0 = 0.f, s1 = 0.f, d0 = 0.f, d1 = 0.f;
#pragma unroll
        for (int nt = 0; nt < NT; nt++) {
#pragma unroll
            for (int q = 0; q < 2; q++) {
                int cl = warpCol + nt * 8 + qc * 2 + q;
                float as = sAs[cl], ad = sAd[cl];
                s0 += acc[mt][nt][q] * as;     d0 += acc[mt][nt][q] * ad;
                s1 += acc[mt][nt][2 + q] * as; d1 += acc[mt][nt][2 + q] * ad;
            }
        }
#pragma unroll
        for (int o = 2; o; o >>= 1) {
            s0 += __shfl_down_sync(0xffffffffu, s0, o, 4);
            s1 += __shfl_down_sync(0xffffffffu, s1, o, 4);
            d0 += __shfl_down_sync(0xffffffffu, d0, o, 4);
            d1 += __shfl_down_sync(0xffffffffu, d1, o, 4);
        }
        if (qc == 0) {
            int rl = warpRow + mt * 16 + qr;
            sRedS[wc * 128 + rl] = s0;  sRedS[wc * 128 + rl + 8] = s1;
            sRedD[wc * 128 + rl] = d0;  sRedD[wc * 128 + rl + 8] = d1;
        }
    }
    __syncthreads();

    if (tid < 128) {
        int grow = rowBase + tid;
        if (grow < M) {
            int hpb = (BN > C) ? (BN / C) : 1;
            int wph = 4 / hpb;
            int headBase = colBase / C;
            for (int hh = 0; hh < hpb; hh++) {
                float as = 0.f, ad = 0.f;
                for (int w = 0; w < wph; w++) {
                    as += sRedS[(hh * wph + w) * 128 + tid];
                    ad += sRedD[(hh * wph + w) * 128 + tid];
                }
                g_asrc[grow * H + headBase + hh] = as;
                g_adst[grow * H + headBase + hh] = ad;
            }
        }
    }
}

// ------- fused per-node softmax stats + gather-aggregate + bias + relu -------
template <int H, int C, bool SPLIT, int NTH>
__global__ void agg_kernel(const float* __restrict__ bias, float* __restrict__ out) {
    constexpr int HC = H * C;
    constexpr int NV = HC / 4;
    constexpr int NW = NTH / 32;
    int d = blockIdx.x;
    int tid = threadIdx.x;
    int lane = tid & 31, w = tid >> 5;
    int start = g_rowptr[d], end = g_rowptr[d + 1];
    int deg = end - start;

    __shared__ float red[H][NW];
    __shared__ float sMax[H], sInv[H];

    float adst[H];
#pragma unroll
    for (int h = 0; h < H; h++) adst[h] = g_adst[d * H + h];

    // pass 1: max
    float lmax[H];
#pragma unroll
    for (int h = 0; h < H; h++) lmax[h] = -INFINITY;
    for (int i = tid; i < deg; i += NTH) {
        int s = g_csr_src[start + i];
#pragma unroll
        for (int h = 0; h < H; h++) {
            float v = g_asrc[s * H + h] + adst[h];
            v = (v > 0.f) ? v : 0.2f * v;
            lmax[h] = fmaxf(lmax[h], v);
        }
    }
#pragma unroll
    for (int h = 0; h < H; h++) {
#pragma unroll
        for (int o = 16; o; o >>= 1)
            lmax[h] = fmaxf(lmax[h], __shfl_xor_sync(0xffffffffu, lmax[h], o));
        if (lane == 0) red[h][w] = lmax[h];
    }
    __syncthreads();
    if (tid < H) {
        float m = red[tid][0];
#pragma unroll
        for (int j = 1; j < NW; j++) m = fmaxf(m, red[tid][j]);
        sMax[tid] = m;
    }
    __syncthreads();

    // pass 2: sum of exp
    float lsum[H];
#pragma unroll
    for (int h = 0; h < H; h++) lsum[h] = 0.f;
    for (int i = tid; i < deg; i += NTH) {
        int s = g_csr_src[start + i];
#pragma unroll
        for (int h = 0; h < H; h++) {
            float v = g_asrc[s * H + h] + adst[h];
            v = (v > 0.f) ? v : 0.2f * v;
            lsum[h] += __expf(v - sMax[h]);
        }
    }
#pragma unroll
    for (int h = 0; h < H; h++) {
#pragma unroll
        for (int o = 16; o; o >>= 1)
            lsum[h] += __shfl_xor_sync(0xffffffffu, lsum[h], o);
        if (lane == 0) red[h][w] = lsum[h];
    }
    __syncthreads();
    if (tid < H) {
        float s = 0.f;
#pragma unroll
        for (int j = 1; j < NW; j++) s += red[tid][j];
        sInv[tid] = 1.f / (red[tid][0] + s);
    }
    __syncthreads();

    // pass 3: gather-aggregate with inline alpha
    if (tid < NV) {
        int c4 = tid * 4;
        int head = c4 / C;
        float bm  = sMax[head];
        float inv = sInv[head];
        float ad  = adst[head];

        float4 acc = make_float4(0.f, 0.f, 0.f, 0.f);
        for (int pos = start; pos < end; pos++) {
            int s = g_csr_src[pos];
            float v = g_asrc[s * H + head] + ad;
            v = (v > 0.f) ? v : 0.2f * v;
            float al = __expf(v - bm) * inv;
            float4 hv = *(const float4*)&g_h[(size_t)s * HC + c4];
            acc.x += hv.x * al; acc.y += hv.y * al;
            acc.z += hv.z * al; acc.w += hv.w * al;
        }
        float4 bv = *(const float4*)&bias[c4];
        acc.x = fmaxf(acc.x + bv.x, 0.f);
        acc.y = fmaxf(acc.y + bv.y, 0.f);
        acc.z = fmaxf(acc.z + bv.z, 0.f);
        acc.w = fmaxf(acc.w + bv.w, 0.f);
        if (SPLIT) {
            size_t base = (size_t)d * HC + c4;
            __nv_bfloat16 h0 = __float2bfloat16(acc.x), h1 = __float2bfloat16(acc.y);
            __nv_bfloat16 h2 = __float2bfloat16(acc.z), h3 = __float2bfloat16(acc.w);
            __nv_bfloat16 l0 = __float2bfloat16(acc.x - __bfloat162float(h0));
            __nv_bfloat16 l1 = __float2bfloat16(acc.y - __bfloat162float(h1));
            __nv_bfloat16 l2 = __float2bfloat16(acc.z - __bfloat162float(h2));
            __nv_bfloat16 l3 = __float2bfloat16(acc.w - __bfloat162float(h3));
            ((__nv_bfloat162*)(g_Ahi + base))[0] = __nv_bfloat162(h0, h1);
            ((__nv_bfloat162*)(g_Ahi + base))[1] = __nv_bfloat162(h2, h3);
            ((__nv_bfloat162*)(g_Alo + base))[0] = __nv_bfloat162(l0, l1);
            ((__nv_bfloat162*)(g_Alo + base))[1] = __nv_bfloat162(l2, l3);
        } else {
            *(float4*)&out[(size_t)d * HC + c4] = acc;
        }
    }
}

// ---------------- driver ------------------------------------------------------
extern "C" void kernel_launch(void* const* d_in, const int* in_sizes, int n_in,
                              void* d_out, int out_size) {
    const float* x  = (const float*)d_in[0];
    const void*  ei = d_in[1];
    float* out = (float*)d_out;

    void* p;
    cudaGetSymbolAddress(&p, g_h);
    float* h_ptr = (float*)p;

    static bool attr_done = false;
    if (!attr_done) {
        cudaFuncSetAttribute(mma_gemm_kernel<128>, cudaFuncAttributeMaxDynamicSharedMemorySize,
                             3 * 16384 + 3 * 128 * 128);
        cudaFuncSetAttribute(mma_gemm_kernel<64>, cudaFuncAttributeMaxDynamicSharedMemorySize,
                             3 * 16384 + 3 * 64 * 128);
        attr_done = true;
    }

    struct Cfg { const float *W, *as, *ad, *b; int Fin, H, C, boff; };
    Cfg cfg[4] = {
        { (const float*)d_in[2],  (const float*)d_in[3],  (const float*)d_in[4],  (const float*)d_in[5],  256, 4, 128, WOFF0 },
        { (const float*)d_in[6],  (const float*)d_in[7],  (const float*)d_in[8],  (const float*)d_in[9],  512, 4, 128, WOFF1 },
        { (const float*)d_in[10], (const float*)d_in[11], (const float*)d_in[12], (const float*)d_in[13], 512, 4,  64, WOFF2 },
        { (const float*)d_in[14], (const float*)d_in[15], (const float*)d_in[16], (const float*)d_in[17], 256, 1,  64, WOFF3 },
    };

    detect_dtype_kernel<<<1, 1>>>((const int*)ei);
    zero_deg_kernel<<<(N_NODES + TPB - 1) / TPB, TPB>>>();
    build_edges_kernel<<<(E_TOT + TPB - 1) / TPB, TPB>>>(ei);
    scan1_kernel<<<NSB, SB>>>();
    scan2_kernel<<<1, 256>>>();
    scan3_kernel<<<NSB, SB>>>();
    scatter_kernel<<<(E_TOT + TPB - 1) / TPB, TPB>>>();

    wsplit_all_kernel<<<528, dim3(32, 8)>>>(cfg[0].W, cfg[1].W, cfg[2].W, cfg[3].W);
    {
        int total4 = N_NODES * 256 / 4;
        split_kernel<<<(total4 + TPB - 1) / TPB, TPB>>>(x, total4);
    }

    const int MT = (N_NODES + 127) / 128;

    for (int L = 0; L < 4; L++) {
        const Cfg& c = cfg[L];
        int HC = c.H * c.C;

        if (HC >= 128) {
            dim3 grid(HC / 128, MT);
            mma_gemm_kernel<128><<<grid, 256, 3 * 16384 + 3 * 128 * 128>>>(
                h_ptr, c.as, c.ad, N_NODES, HC, c.Fin, c.H, c.C, c.boff);
        } else {
            dim3 grid(HC / 64, MT);
            mma_gemm_kernel<64><<<grid, 256, 3 * 16384 + 3 * 64 * 128>>>(
                h_ptr, c.as, c.ad, N_NODES, HC, c.Fin, c.H, c.C, c.boff);
        }

        switch (L) {
            case 0:
                agg_kernel<4, 128, true, 128><<<N_NODES, 128>>>(c.b, nullptr);
                break;
            case 1:
                agg_kernel<4, 128, true, 128><<<N_NODES, 128>>>(c.b, nullptr);
                break;
            case 2:
                agg_kernel<4, 64, true, 64><<<N_NODES, 64>>>(c.b, nullptr);
                break;
            case 3:
                agg_kernel<1, 64, false, 32><<<N_NODES, 32>>>(c.b, out);
                break;
        }
    }
}